// round 11
// baseline (speedup 1.0000x reference)
#include <cuda_runtime.h>
#include <cuda_bf16.h>
#include <cuda_fp16.h>
#include <cstdint>

#define NN 50000
#define NNPAD 50048       // NN rounded up to 128 (zero-init padding rows)
#define NE 800000
#define DIM 128
#define NR 8
#define NOUT (NR * DIM)   // 1024 = Y row length
#define NBLK 196          // scan blocks: 196*256 = 50176 >= NN

// ---------------- scratch (device globals: allocation-free, zero-init) ----------------
__device__ __align__(16) __half g_Y[(size_t)NN * NOUT];      // 102.4 MB projected features
__device__ float g_h[(size_t)NN * DIM];                      // layer-1 output (fp32)
__device__ __align__(16) __nv_bfloat16 g_Ahi[(size_t)NNPAD * DIM]; // A split hi/lo
__device__ __align__(16) __nv_bfloat16 g_Alo[(size_t)NNPAD * DIM];
__device__ __align__(16) __nv_bfloat16 g_Whi1[NOUT * DIM];   // Wt hi/lo, [n=r*128+o][k=i]
__device__ __align__(16) __nv_bfloat16 g_Wlo1[NOUT * DIM];
__device__ __align__(16) __nv_bfloat16 g_Whi2[NOUT * DIM];
__device__ __align__(16) __nv_bfloat16 g_Wlo2[NOUT * DIM];
// CSR-by-dst structures
__device__ int   g_cnt[NBLK * 256];
__device__ int   g_bsum[256];
__device__ int   g_bpre[256];
__device__ int   g_off[NBLK * 256 + 1];
__device__ int   g_pos[NBLK * 256];
__device__ int   g_psr[NE];                // packed (etype<<24)|src, permuted
__device__ float g_pw[NE];                 // edge weight, permuted

__device__ __forceinline__ uint32_t smem_u32(const void* p) {
    uint32_t a;
    asm("{ .reg .u64 t; cvta.to.shared.u64 t, %1; cvt.u32.u64 %0, t; }" : "=r"(a) : "l"(p));
    return a;
}

// ---------------- A pre-conversion: fp32 -> bf16 hi/lo (relu optional) ----------------
template<bool RELU>
__global__ void conv_A(const float4* __restrict__ A, uint2* __restrict__ Ahi,
                       uint2* __restrict__ Alo) {
    int idx = blockIdx.x * blockDim.x + threadIdx.x;   // NN*32 = 1.6M float4
    float4 v = A[idx];
    if (RELU) {
        v.x = fmaxf(v.x, 0.f); v.y = fmaxf(v.y, 0.f);
        v.z = fmaxf(v.z, 0.f); v.w = fmaxf(v.w, 0.f);
    }
    __nv_bfloat16 hx = __float2bfloat16(v.x), hy = __float2bfloat16(v.y);
    __nv_bfloat16 hz = __float2bfloat16(v.z), hw = __float2bfloat16(v.w);
    __nv_bfloat16 lx = __float2bfloat16(v.x - __bfloat162float(hx));
    __nv_bfloat16 ly = __float2bfloat16(v.y - __bfloat162float(hy));
    __nv_bfloat16 lz = __float2bfloat16(v.z - __bfloat162float(hz));
    __nv_bfloat16 lw = __float2bfloat16(v.w - __bfloat162float(hw));
    uint2 h, l;
    h.x = (uint32_t)__bfloat16_as_ushort(hx) | ((uint32_t)__bfloat16_as_ushort(hy) << 16);
    h.y = (uint32_t)__bfloat16_as_ushort(hz) | ((uint32_t)__bfloat16_as_ushort(hw) << 16);
    l.x = (uint32_t)__bfloat16_as_ushort(lx) | ((uint32_t)__bfloat16_as_ushort(ly) << 16);
    l.y = (uint32_t)__bfloat16_as_ushort(lz) | ((uint32_t)__bfloat16_as_ushort(lw) << 16);
    Ahi[idx] = h;
    Alo[idx] = l;
}

// ---------------- W composition: Wt[n][k] split into bf16 hi/lo ----------------
__global__ void compute_Wt(const float* __restrict__ comp, const float* __restrict__ V,
                           __nv_bfloat16* __restrict__ Whi, __nv_bfloat16* __restrict__ Wlo) {
    int idx = blockIdx.x * blockDim.x + threadIdx.x;   // 131072
    int r = idx >> 14;
    int io = idx & 16383;
    int i = io >> 7;
    int o = io & 127;
    float acc = 0.f;
#pragma unroll
    for (int b = 0; b < NR; b++)
        acc += comp[r * NR + b] * V[b * 16384 + io];
    __nv_bfloat16 hi = __float2bfloat16(acc);
    __nv_bfloat16 lo = __float2bfloat16(acc - __bfloat162float(hi));
    int n = r * DIM + o;
    Whi[(size_t)n * DIM + i] = hi;
    Wlo[(size_t)n * DIM + i] = lo;
}

// ---------------- CSR build ----------------
__global__ void hist(const int* __restrict__ dst) {
    int e = blockIdx.x * blockDim.x + threadIdx.x;
    if (e < NE) atomicAdd(&g_cnt[dst[e]], 1);
}
__global__ void scan1() {
    __shared__ int s[256];
    int t = threadIdx.x;
    int v = g_cnt[blockIdx.x * 256 + t];
    s[t] = v; __syncthreads();
#pragma unroll
    for (int o = 1; o < 256; o <<= 1) {
        int x = (t >= o) ? s[t - o] : 0; __syncthreads();
        s[t] += x; __syncthreads();
    }
    if (t == 255) g_bsum[blockIdx.x] = s[255];
}
__global__ void scan2() {
    __shared__ int s[256];
    int t = threadIdx.x;
    int v = (t < NBLK) ? g_bsum[t] : 0;
    s[t] = v; __syncthreads();
#pragma unroll
    for (int o = 1; o < 256; o <<= 1) {
        int x = (t >= o) ? s[t - o] : 0; __syncthreads();
        s[t] += x; __syncthreads();
    }
    if (t < NBLK) g_bpre[t] = s[t] - v;
}
__global__ void scan3() {
    __shared__ int s[256];
    int t = threadIdx.x;
    int i = blockIdx.x * 256 + t;
    int v = g_cnt[i];
    s[t] = v; __syncthreads();
#pragma unroll
    for (int o = 1; o < 256; o <<= 1) {
        int x = (t >= o) ? s[t - o] : 0; __syncthreads();
        s[t] += x; __syncthreads();
    }
    g_off[i] = g_bpre[blockIdx.x] + s[t] - v;
    if (i == NBLK * 256 - 1) g_off[NBLK * 256] = NE;
}
__global__ void permute(const int* __restrict__ src, const int* __restrict__ dst,
                        const int* __restrict__ et, const float* __restrict__ w) {
    int e = blockIdx.x * blockDim.x + threadIdx.x;
    if (e >= NE) return;
    int d = dst[e];
    int p = atomicAdd(&g_pos[d], 1);
    g_psr[p] = (et[e] << 24) | src[e];
    g_pw[p]  = w[e];
}

// ---------------- gather: one warp per node ----------------
__global__ void __launch_bounds__(256) gather(const __half* __restrict__ Y,
                                              const float* __restrict__ bias,
                                              float* __restrict__ out) {
    int wid = threadIdx.x >> 5, lane = threadIdx.x & 31;
    int n = blockIdx.x * 8 + wid;
    if (n >= NN) return;
    int beg = g_off[n], end = g_off[n + 1];
    float4 acc = *(const float4*)(bias + lane * 4);
    for (int j = beg; j < end; j++) {
        int sr   = g_psr[j];
        float we = g_pw[j];
        int s = sr & 0xFFFFFF;
        int r = sr >> 24;
        uint2 v = *(const uint2*)(Y + (size_t)s * NOUT + r * DIM + lane * 4);
        float2 f0 = __half22float2(*(const __half2*)&v.x);
        float2 f1 = __half22float2(*(const __half2*)&v.y);
        acc.x = fmaf(we, f0.x, acc.x);
        acc.y = fmaf(we, f0.y, acc.y);
        acc.z = fmaf(we, f1.x, acc.z);
        acc.w = fmaf(we, f1.y, acc.w);
    }
    *(float4*)(out + (size_t)n * DIM + lane * 4) = acc;
}

// ---------------- split-bf16 HMMA GEMM: Y = A @ Wt^T (fp16 out) ----------------
// A pre-split bf16 hi/lo in gmem. M=50000, N=1024, K=128.
// BM=128, BN=128; full K prefetched as 2 cp.async stages (BK=64 each), overlapped.
#define ASTR 144
#define STG 73728         // bytes per kc stage (4 tiles x 18432)
#define SM_TOT (2 * STG)  // 147456

__device__ __forceinline__ void ldsm_x4(uint32_t* r, uint32_t addr) {
    asm volatile("ldmatrix.sync.aligned.m8n8.x4.shared.b16 {%0,%1,%2,%3}, [%4];"
                 : "=r"(r[0]), "=r"(r[1]), "=r"(r[2]), "=r"(r[3]) : "r"(addr));
}
__device__ __forceinline__ void mma16816(float* c, const uint32_t* a, const uint32_t* b) {
    asm volatile(
        "mma.sync.aligned.m16n8k16.row.col.f32.bf16.bf16.f32 "
        "{%0,%1,%2,%3}, {%4,%5,%6,%7}, {%8,%9}, {%0,%1,%2,%3};"
        : "+f"(c[0]), "+f"(c[1]), "+f"(c[2]), "+f"(c[3])
        : "r"(a[0]), "r"(a[1]), "r"(a[2]), "r"(a[3]), "r"(b[0]), "r"(b[1]));
}

__global__ void __launch_bounds__(256) gemm_y(const __nv_bfloat16* __restrict__ Ahi,
                                              const __nv_bfloat16* __restrict__ Alo,
                                              const __nv_bfloat16* __restrict__ Bhi,
                                              const __nv_bfloat16* __restrict__ Blo,
                                              __half* __restrict__ Y) {
    extern __shared__ char dsm[];
    uint32_t sb = smem_u32(dsm);
    int t = threadIdx.x;
    int lane = t & 31, wid = t >> 5;
    int warp_m = wid >> 2, warp_n = wid & 3;
    int m0 = blockIdx.x * 128;
    int n0 = blockIdx.y * 128;

    // ---- prologue: issue both kc stages (separate commit groups) ----
#pragma unroll
    for (int kc = 0; kc < 2; kc++) {
#pragma unroll
        for (int j = 0; j < 16; j++) {
            int lin = t + j * 256;                 // 0..4095
            int tile = lin >> 10;                  // 0=Ahi 1=Alo 2=Bhi 3=Blo
            int l2 = lin & 1023;
            int row = l2 >> 3, q = l2 & 7;         // 8 x 16B per row
            const __nv_bfloat16* gp;
            if      (tile == 0) gp = Ahi + (size_t)(m0 + row) * DIM + kc * 64 + q * 8;
            else if (tile == 1) gp = Alo + (size_t)(m0 + row) * DIM + kc * 64 + q * 8;
            else if (tile == 2) gp = Bhi + (size_t)(n0 + row) * DIM + kc * 64 + q * 8;
            else                gp = Blo + (size_t)(n0 + row) * DIM + kc * 64 + q * 8;
            uint32_t db = sb + kc * STG + tile * 18432 + row * ASTR + q * 16;
            asm volatile("cp.async.ca.shared.global [%0], [%1], 16;"
                         :: "r"(db), "l"(gp) : "memory");
        }
        asm volatile("cp.async.commit_group;" ::: "memory");
    }

    float acc[4][4][4] = {};

#pragma unroll
    for (int kc = 0; kc < 2; kc++) {
        if (kc == 0) asm volatile("cp.async.wait_group 1;" ::: "memory");
        else         asm volatile("cp.async.wait_group 0;" ::: "memory");
        __syncthreads();
        uint32_t base = sb + kc * STG;
#pragma unroll
        for (int ks = 0; ks < 4; ks++) {
            uint32_t bhi[2][4], blo[2][4];
            int brow = warp_n * 32 + ((lane >> 4) & 1) * 8 + (lane & 7);
            uint32_t bcol = ks * 32 + ((lane >> 3) & 1) * 16;
#pragma unroll
            for (int pr = 0; pr < 2; pr++) {
                uint32_t boff = (brow + pr * 16) * ASTR + bcol;
                ldsm_x4(bhi[pr], base + 36864 + boff);
                ldsm_x4(blo[pr], base + 55296 + boff);
            }
#pragma unroll
            for (int mt = 0; mt < 4; mt++) {
                uint32_t ahi[4], alo[4];
                int arow = warp_m * 64 + mt * 16 + (lane & 15);
                uint32_t aoff = arow * ASTR + ks * 32 + (lane >> 4) * 16;
                ldsm_x4(ahi, base + aoff);
                ldsm_x4(alo, base + 18432 + aoff);
#pragma unroll
                for (int nt = 0; nt < 4; nt++) {
                    const uint32_t* bh = &bhi[nt >> 1][(nt & 1) * 2];
                    const uint32_t* bl = &blo[nt >> 1][(nt & 1) * 2];
                    mma16816(acc[mt][nt], ahi, bh);
                    mma16816(acc[mt][nt], ahi, bl);
                    mma16816(acc[mt][nt], alo, bh);
                }
            }
        }
    }

    // ---- epilogue: Y in fp16 ----
    int group = lane >> 2, tig = lane & 3;
#pragma unroll
    for (int mt = 0; mt < 4; mt++) {
#pragma unroll
        for (int half = 0; half < 2; half++) {
            int row = m0 + warp_m * 64 + mt * 16 + group + half * 8;
            if (row < NN) {
#pragma unroll
                for (int nt = 0; nt < 4; nt++) {
                    int col = n0 + warp_n * 32 + nt * 8 + 2 * tig;
                    __half2 hv = __floats2half2_rn(acc[mt][nt][half * 2 + 0],
                                                   acc[mt][nt][half * 2 + 1]);
                    *(__half2*)(Y + (size_t)row * NOUT + col) = hv;
                }
            }
        }
    }
}

// ---------------- launch ----------------
extern "C" void kernel_launch(void* const* d_in, const int* in_sizes, int n_in,
                              void* d_out, int out_size) {
    const float* features = (const float*)d_in[0];
    const int*   etypes   = (const int*)d_in[1];
    const float* ew       = (const float*)d_in[2];
    const int*   src      = (const int*)d_in[3];
    const int*   dst      = (const int*)d_in[4];
    const float* comp1    = (const float*)d_in[5];
    const float* V1       = (const float*)d_in[6];
    const float* bias1    = (const float*)d_in[7];
    const float* comp2    = (const float*)d_in[8];
    const float* V2       = (const float*)d_in[9];
    const float* bias2    = (const float*)d_in[10];
    float* out = (float*)d_out;

    __half* Yp;
    float* hp;
    __nv_bfloat16 *Ahi, *Alo, *Whi1, *Wlo1, *Whi2, *Wlo2;
    int *cntp, *offp, *posp;
    cudaGetSymbolAddress((void**)&Yp,   g_Y);
    cudaGetSymbolAddress((void**)&hp,   g_h);
    cudaGetSymbolAddress((void**)&Ahi,  g_Ahi);
    cudaGetSymbolAddress((void**)&Alo,  g_Alo);
    cudaGetSymbolAddress((void**)&Whi1, g_Whi1);
    cudaGetSymbolAddress((void**)&Wlo1, g_Wlo1);
    cudaGetSymbolAddress((void**)&Whi2, g_Whi2);
    cudaGetSymbolAddress((void**)&Wlo2, g_Wlo2);
    cudaGetSymbolAddress((void**)&cntp, g_cnt);
    cudaGetSymbolAddress((void**)&offp, g_off);
    cudaGetSymbolAddress((void**)&posp, g_pos);

    cudaFuncSetAttribute(gemm_y, cudaFuncAttributeMaxDynamicSharedMemorySize, SM_TOT);

    // Weights
    compute_Wt<<<512, 256>>>(comp1, V1, Whi1, Wlo1);
    compute_Wt<<<512, 256>>>(comp2, V2, Whi2, Wlo2);

    // CSR build (graph shared by both layers)
    cudaMemsetAsync(cntp, 0, NBLK * 256 * sizeof(int));
    hist<<<(NE + 255) / 256, 256>>>(dst);
    scan1<<<NBLK, 256>>>();
    scan2<<<1, 256>>>();
    scan3<<<NBLK, 256>>>();
    cudaMemcpyAsync(posp, offp, NBLK * 256 * sizeof(int), cudaMemcpyDeviceToDevice);
    permute<<<(NE + 255) / 256, 256>>>(src, dst, etypes, ew);

    dim3 ggrid((NN + 127) / 128, NR);   // 391 x 8
    const int GB = (NN + 7) / 8;        // 6250
    const int CB = NN * 32 / 256;       // 6250 (conv_A blocks)

    // Layer 1: A = split(X) ; Y = A @ W1 ; h = bias1 + gather(Y)
    conv_A<false><<<CB, 256>>>((const float4*)features, (uint2*)Ahi, (uint2*)Alo);
    gemm_y<<<ggrid, 256, SM_TOT>>>(Ahi, Alo, Whi1, Wlo1, Yp);
    gather<<<GB, 256>>>(Yp, bias1, hp);

    // Layer 2: A = split(relu(h)) ; Y = A @ W2 ; out = bias2 + gather(Y)
    conv_A<true><<<CB, 256>>>((const float4*)hp, (uint2*)Ahi, (uint2*)Alo);
    gemm_y<<<ggrid, 256, SM_TOT>>>(Ahi, Alo, Whi2, Wlo2, Yp);
    gather<<<GB, 256>>>(Yp, bias2, out);
}

// round 13
// speedup vs baseline: 1.5186x; 1.5186x over previous
#include <cuda_runtime.h>
#include <cuda_fp16.h>
#include <cstdint>

#define NN 50000
#define NNPAD 50048       // NN rounded up to 128 (zero-init padding rows)
#define NE 800000
#define DIM 128
#define NR 8
#define NOUT (NR * DIM)   // 1024 = Y row length
#define NBLK 196          // scan blocks: 196*256 = 50176 >= NN

// ---------------- scratch (device globals: allocation-free, zero-init) ----------------
__device__ __align__(16) __half g_Y[(size_t)NN * NOUT];      // 102.4 MB projected features
__device__ float g_h[(size_t)NN * DIM];                      // layer-1 output (fp32)
__device__ __align__(16) __half g_A[(size_t)NNPAD * DIM];    // A as fp16
__device__ __align__(16) __half g_W1[NOUT * DIM];            // Wt fp16, [n=r*128+o][k=i]
__device__ __align__(16) __half g_W2[NOUT * DIM];
// CSR-by-dst structures
__device__ int   g_cnt[NBLK * 256];
__device__ int   g_bsum[256];
__device__ int   g_bpre[256];
__device__ int   g_off[NBLK * 256 + 1];
__device__ int   g_pos[NBLK * 256];
__device__ int   g_psr[NE];                // packed (etype<<24)|src, permuted
__device__ float g_pw[NE];                 // edge weight, permuted

__device__ __forceinline__ uint32_t smem_u32(const void* p) {
    uint32_t a;
    asm("{ .reg .u64 t; cvta.to.shared.u64 t, %1; cvt.u32.u64 %0, t; }" : "=r"(a) : "l"(p));
    return a;
}

// ---------------- CSR counter zero (kernel, not memset: keeps launch index fixed) ----
__global__ void zero_cnt() {
    g_cnt[blockIdx.x * 256 + threadIdx.x] = 0;
}

// ---------------- CSR histogram ----------------
__global__ void hist(const int* __restrict__ dst) {
    int e = blockIdx.x * blockDim.x + threadIdx.x;
    if (e < NE) atomicAdd(&g_cnt[dst[e]], 1);
}

// ---------------- W composition: Wt[n][k] in fp16 ----------------
__global__ void compute_Wt(const float* __restrict__ comp, const float* __restrict__ V,
                           __half* __restrict__ W) {
    int idx = blockIdx.x * blockDim.x + threadIdx.x;   // 131072
    int r = idx >> 14;
    int io = idx & 16383;
    int i = io >> 7;
    int o = io & 127;
    float acc = 0.f;
#pragma unroll
    for (int b = 0; b < NR; b++)
        acc += comp[r * NR + b] * V[b * 16384 + io];
    int n = r * DIM + o;
    W[(size_t)n * DIM + i] = __float2half_rn(acc);
}

// ---------------- A conversion: fp32 -> fp16 (relu optional) ----------------
template<bool RELU>
__global__ void conv_A(const float4* __restrict__ A, uint2* __restrict__ Ah) {
    int idx = blockIdx.x * blockDim.x + threadIdx.x;   // NN*32 = 1.6M float4
    float4 v = A[idx];
    if (RELU) {
        v.x = fmaxf(v.x, 0.f); v.y = fmaxf(v.y, 0.f);
        v.z = fmaxf(v.z, 0.f); v.w = fmaxf(v.w, 0.f);
    }
    __half2 h0 = __floats2half2_rn(v.x, v.y);
    __half2 h1 = __floats2half2_rn(v.z, v.w);
    uint2 o;
    o.x = *(const uint32_t*)&h0;
    o.y = *(const uint32_t*)&h1;
    Ah[idx] = o;
}

// ---------------- fp16 HMMA GEMM: Y = A @ Wt^T (fp16 out, fp32 accum) ----------------
// M=50000, N=1024, K=128. BM=128, BN=128; full K as 2 cp.async stages (BK=64), occ 2.
#define ASTR 144          // smem row stride bytes (64 half = 128B data + 16B pad)
#define TILE_B 18432      // 128 rows * 144
#define STG (2 * TILE_B)  // A + B per kc stage
#define SM_TOT (2 * STG)  // 73728

__device__ __forceinline__ void ldsm_x4(uint32_t* r, uint32_t addr) {
    asm volatile("ldmatrix.sync.aligned.m8n8.x4.shared.b16 {%0,%1,%2,%3}, [%4];"
                 : "=r"(r[0]), "=r"(r[1]), "=r"(r[2]), "=r"(r[3]) : "r"(addr));
}
__device__ __forceinline__ void mma16816(float* c, const uint32_t* a, const uint32_t* b) {
    asm volatile(
        "mma.sync.aligned.m16n8k16.row.col.f32.f16.f16.f32 "
        "{%0,%1,%2,%3}, {%4,%5,%6,%7}, {%8,%9}, {%0,%1,%2,%3};"
        : "+f"(c[0]), "+f"(c[1]), "+f"(c[2]), "+f"(c[3])
        : "r"(a[0]), "r"(a[1]), "r"(a[2]), "r"(a[3]), "r"(b[0]), "r"(b[1]));
}

__global__ void __launch_bounds__(256, 2) gemm_y(const __half* __restrict__ A,
                                                 const __half* __restrict__ B,
                                                 __half* __restrict__ Y) {
    extern __shared__ char dsm[];
    uint32_t sb = smem_u32(dsm);
    int t = threadIdx.x;
    int lane = t & 31, wid = t >> 5;
    int warp_m = wid >> 2, warp_n = wid & 3;
    int m0 = blockIdx.x * 128;
    int n0 = blockIdx.y * 128;

    // ---- prologue: issue both kc stages as separate commit groups ----
#pragma unroll
    for (int kc = 0; kc < 2; kc++) {
#pragma unroll
        for (int j = 0; j < 8; j++) {
            int lin = t + j * 256;                 // 0..2047
            int tile = lin >> 10;                  // 0=A 1=B
            int l2 = lin & 1023;
            int row = l2 >> 3, q = l2 & 7;         // 8 x 16B per row
            const __half* gp = (tile == 0)
                ? A + (size_t)(m0 + row) * DIM + kc * 64 + q * 8
                : B + (size_t)(n0 + row) * DIM + kc * 64 + q * 8;
            uint32_t db = sb + kc * STG + tile * TILE_B + row * ASTR + q * 16;
            asm volatile("cp.async.ca.shared.global [%0], [%1], 16;"
                         :: "r"(db), "l"(gp) : "memory");
        }
        asm volatile("cp.async.commit_group;" ::: "memory");
    }

    float acc[4][4][4] = {};   // [mt][nt][4]

#pragma unroll
    for (int kc = 0; kc < 2; kc++) {
        if (kc == 0) asm volatile("cp.async.wait_group 1;" ::: "memory");
        else         asm volatile("cp.async.wait_group 0;" ::: "memory");
        __syncthreads();
        uint32_t abase = sb + kc * STG;
        uint32_t bbase = abase + TILE_B;
#pragma unroll
        for (int ks = 0; ks < 4; ks++) {
            uint32_t bf[2][4];
            int brow = warp_n * 32 + ((lane >> 4) & 1) * 8 + (lane & 7);
            uint32_t bcol = ks * 32 + ((lane >> 3) & 1) * 16;
#pragma unroll
            for (int pr = 0; pr < 2; pr++)
                ldsm_x4(bf[pr], bbase + (brow + pr * 16) * ASTR + bcol);
#pragma unroll
            for (int mt = 0; mt < 4; mt++) {
                uint32_t af[4];
                int arow = warp_m * 64 + mt * 16 + (lane & 15);
                ldsm_x4(af, abase + arow * ASTR + ks * 32 + (lane >> 4) * 16);
#pragma unroll
                for (int nt = 0; nt < 4; nt++)
                    mma16816(acc[mt][nt], af, &bf[nt >> 1][(nt & 1) * 2]);
            }
        }
    }

    // ---- epilogue: Y in fp16 ----
    int group = lane >> 2, tig = lane & 3;
#pragma unroll
    for (int mt = 0; mt < 4; mt++) {
#pragma unroll
        for (int half = 0; half < 2; half++) {
            int row = m0 + warp_m * 64 + mt * 16 + group + half * 8;
            if (row < NN) {
#pragma unroll
                for (int nt = 0; nt < 4; nt++) {
                    int col = n0 + warp_n * 32 + nt * 8 + 2 * tig;
                    __half2 hv = __floats2half2_rn(acc[mt][nt][half * 2 + 0],
                                                   acc[mt][nt][half * 2 + 1]);
                    *(__half2*)(Y + (size_t)row * NOUT + col) = hv;
                }
            }
        }
    }
}

// ---------------- CSR scans ----------------
__global__ void scan1() {
    __shared__ int s[256];
    int t = threadIdx.x;
    int v = g_cnt[blockIdx.x * 256 + t];
    s[t] = v; __syncthreads();
#pragma unroll
    for (int o = 1; o < 256; o <<= 1) {
        int x = (t >= o) ? s[t - o] : 0; __syncthreads();
        s[t] += x; __syncthreads();
    }
    if (t == 255) g_bsum[blockIdx.x] = s[255];
}
__global__ void scan2() {
    __shared__ int s[256];
    int t = threadIdx.x;
    int v = (t < NBLK) ? g_bsum[t] : 0;
    s[t] = v; __syncthreads();
#pragma unroll
    for (int o = 1; o < 256; o <<= 1) {
        int x = (t >= o) ? s[t - o] : 0; __syncthreads();
        s[t] += x; __syncthreads();
    }
    if (t < NBLK) g_bpre[t] = s[t] - v;
}
__global__ void scan3() {
    __shared__ int s[256];
    int t = threadIdx.x;
    int i = blockIdx.x * 256 + t;
    int v = g_cnt[i];
    s[t] = v; __syncthreads();
#pragma unroll
    for (int o = 1; o < 256; o <<= 1) {
        int x = (t >= o) ? s[t - o] : 0; __syncthreads();
        s[t] += x; __syncthreads();
    }
    g_off[i] = g_bpre[blockIdx.x] + s[t] - v;
    if (i == NBLK * 256 - 1) g_off[NBLK * 256] = NE;
}
__global__ void permute(const int* __restrict__ src, const int* __restrict__ dst,
                        const int* __restrict__ et, const float* __restrict__ w) {
    int e = blockIdx.x * blockDim.x + threadIdx.x;
    if (e >= NE) return;
    int d = dst[e];
    int p = atomicAdd(&g_pos[d], 1);
    g_psr[p] = (et[e] << 24) | src[e];
    g_pw[p]  = w[e];
}

// ---------------- gather: one warp per node ----------------
__global__ void __launch_bounds__(256) gather(const __half* __restrict__ Y,
                                              const float* __restrict__ bias,
                                              float* __restrict__ out) {
    int wid = threadIdx.x >> 5, lane = threadIdx.x & 31;
    int n = blockIdx.x * 8 + wid;
    if (n >= NN) return;
    int beg = g_off[n], end = g_off[n + 1];
    float4 acc = *(const float4*)(bias + lane * 4);
    for (int j = beg; j < end; j++) {
        int sr   = g_psr[j];
        float we = g_pw[j];
        int s = sr & 0xFFFFFF;
        int r = sr >> 24;
        uint2 v = *(const uint2*)(Y + (size_t)s * NOUT + r * DIM + lane * 4);
        float2 f0 = __half22float2(*(const __half2*)&v.x);
        float2 f1 = __half22float2(*(const __half2*)&v.y);
        acc.x = fmaf(we, f0.x, acc.x);
        acc.y = fmaf(we, f0.y, acc.y);
        acc.z = fmaf(we, f1.x, acc.z);
        acc.w = fmaf(we, f1.y, acc.w);
    }
    *(float4*)(out + (size_t)n * DIM + lane * 4) = acc;
}

// ---------------- launch ----------------
extern "C" void kernel_launch(void* const* d_in, const int* in_sizes, int n_in,
                              void* d_out, int out_size) {
    const float* features = (const float*)d_in[0];
    const int*   etypes   = (const int*)d_in[1];
    const float* ew       = (const float*)d_in[2];
    const int*   src      = (const int*)d_in[3];
    const int*   dst      = (const int*)d_in[4];
    const float* comp1    = (const float*)d_in[5];
    const float* V1       = (const float*)d_in[6];
    const float* bias1    = (const float*)d_in[7];
    const float* comp2    = (const float*)d_in[8];
    const float* V2       = (const float*)d_in[9];
    const float* bias2    = (const float*)d_in[10];
    float* out = (float*)d_out;

    __half *Yp, *Ap, *W1p, *W2p;
    float* hp;
    int *offp, *posp;
    cudaGetSymbolAddress((void**)&Yp,   g_Y);
    cudaGetSymbolAddress((void**)&hp,   g_h);
    cudaGetSymbolAddress((void**)&Ap,   g_A);
    cudaGetSymbolAddress((void**)&W1p,  g_W1);
    cudaGetSymbolAddress((void**)&W2p,  g_W2);
    cudaGetSymbolAddress((void**)&offp, g_off);
    cudaGetSymbolAddress((void**)&posp, g_pos);

    cudaFuncSetAttribute(gemm_y, cudaFuncAttributeMaxDynamicSharedMemorySize, SM_TOT);

    dim3 ggrid((NN + 127) / 128, NR);   // 391 x 8
    const int GB = (NN + 7) / 8;        // 6250
    const int CB = NN * 32 / 256;       // 6250

    // Launch order fixed so gemm_y is the 6th kernel (ncu -s 5 -c 1 profiles it).
    zero_cnt<<<NBLK, 256>>>();                                   // 1
    hist<<<(NE + 255) / 256, 256>>>(dst);                        // 2
    compute_Wt<<<512, 256>>>(comp1, V1, W1p);                    // 3
    compute_Wt<<<512, 256>>>(comp2, V2, W2p);                    // 4
    conv_A<false><<<CB, 256>>>((const float4*)features, (uint2*)Ap); // 5
    gemm_y<<<ggrid, 256, SM_TOT>>>(Ap, W1p, Yp);                 // 6  <- profiled
    scan1<<<NBLK, 256>>>();                                      // 7
    scan2<<<1, 256>>>();                                         // 8
    scan3<<<NBLK, 256>>>();                                      // 9
    cudaMemcpyAsync(posp, offp, NBLK * 256 * sizeof(int), cudaMemcpyDeviceToDevice);
    permute<<<(NE + 255) / 256, 256>>>(src, dst, etypes, ew);    // 10
    gather<<<GB, 256>>>(Yp, bias1, hp);                          // 11

    conv_A<true><<<CB, 256>>>((const float4*)hp, (uint2*)Ap);    // 12
    gemm_y<<<ggrid, 256, SM_TOT>>>(Ap, W2p, Yp);                 // 13
    gather<<<GB, 256>>>(Yp, bias2, out);                         // 14
}

// round 17
// speedup vs baseline: 1.6642x; 1.0959x over previous
#include <cuda_runtime.h>
#include <cuda_fp16.h>
#include <cstdint>

#define NN 50000
#define NNPAD 50048       // NN rounded up to 128 (zero-init padding rows)
#define NE 800000
#define DIM 128
#define NR 8
#define NOUT (NR * DIM)   // 1024 = Y row length
#define NBLK 196          // scan blocks: 196*256 = 50176 >= NN

// ---------------- scratch (device globals: allocation-free, zero-init) ----------------
__device__ __align__(16) __half g_Y[(size_t)NN * NOUT];      // 102.4 MB projected features
__device__ __align__(16) __half g_A[(size_t)NNPAD * DIM];    // A as fp16 (relu'd for layer 2)
__device__ __align__(16) __half g_W1[NOUT * DIM];            // Wt fp16, [n=r*128+o][k=i]
__device__ __align__(16) __half g_W2[NOUT * DIM];
// CSR-by-dst structures
__device__ int   g_cnt[NBLK * 256];
__device__ int   g_bsum[256];
__device__ int   g_bpre[256];
__device__ int   g_off[NBLK * 256 + 1];
__device__ int   g_pos[NBLK * 256];
__device__ int   g_psr[NE];                // packed (etype<<24)|src, permuted
__device__ float g_pw[NE];                 // edge weight, permuted

__device__ __forceinline__ uint32_t smem_u32(const void* p) {
    uint32_t a;
    asm("{ .reg .u64 t; cvta.to.shared.u64 t, %1; cvt.u32.u64 %0, t; }" : "=r"(a) : "l"(p));
    return a;
}

// ---------------- small kernels ----------------
__global__ void zero_cnt() {
    g_cnt[blockIdx.x * 256 + threadIdx.x] = 0;
}
__global__ void hist(const int* __restrict__ dst) {
    int e = blockIdx.x * blockDim.x + threadIdx.x;
    if (e < NE) atomicAdd(&g_cnt[dst[e]], 1);
}
__global__ void compute_Wt(const float* __restrict__ comp, const float* __restrict__ V,
                           __half* __restrict__ W) {
    int idx = blockIdx.x * blockDim.x + threadIdx.x;   // 131072
    int r = idx >> 14;
    int io = idx & 16383;
    int i = io >> 7;
    int o = io & 127;
    float acc = 0.f;
#pragma unroll
    for (int b = 0; b < NR; b++)
        acc += comp[r * NR + b] * V[b * 16384 + io];
    int n = r * DIM + o;
    W[(size_t)n * DIM + i] = __float2half_rn(acc);
}
__global__ void conv_A(const float4* __restrict__ A, uint2* __restrict__ Ah) {
    int idx = blockIdx.x * blockDim.x + threadIdx.x;   // NN*32 = 1.6M float4
    float4 v = A[idx];
    __half2 h0 = __floats2half2_rn(v.x, v.y);
    __half2 h1 = __floats2half2_rn(v.z, v.w);
    uint2 o;
    o.x = *(const uint32_t*)&h0;
    o.y = *(const uint32_t*)&h1;
    Ah[idx] = o;
}

// ---------------- fp16 HMMA GEMM: Y = A @ Wt^T (fp16 out, fp32 accum) ----------------
// A tile (128 rows x full K=128) resident in smem; loop over 8 N-tiles with
// double-buffered B chunks (BK=64). grid = (391, 1). occ 2.
#define A_STR 272         // A smem row stride bytes (256B data + 16B pad; 68 banks ≡ 4 mod 32)
#define SM_A_SZ (128 * A_STR)          // 34816
#define B_STR 144         // B smem row stride bytes (128B data + 16B pad)
#define B_TILE (128 * B_STR)           // 18432 per buffer
#define SM_TOT (SM_A_SZ + 2 * B_TILE)  // 71680

__device__ __forceinline__ void ldsm_x4(uint32_t* r, uint32_t addr) {
    asm volatile("ldmatrix.sync.aligned.m8n8.x4.shared.b16 {%0,%1,%2,%3}, [%4];"
                 : "=r"(r[0]), "=r"(r[1]), "=r"(r[2]), "=r"(r[3]) : "r"(addr));
}
__device__ __forceinline__ void mma16816(float* c, const uint32_t* a, const uint32_t* b) {
    asm volatile(
        "mma.sync.aligned.m16n8k16.row.col.f32.f16.f16.f32 "
        "{%0,%1,%2,%3}, {%4,%5,%6,%7}, {%8,%9}, {%0,%1,%2,%3};"
        : "+f"(c[0]), "+f"(c[1]), "+f"(c[2]), "+f"(c[3])
        : "r"(a[0]), "r"(a[1]), "r"(a[2]), "r"(a[3]), "r"(b[0]), "r"(b[1]));
}

__global__ void __launch_bounds__(256, 2) gemm_y(const __half* __restrict__ A,
                                                 const __half* __restrict__ B,
                                                 __half* __restrict__ Y) {
    extern __shared__ char dsm[];
    uint32_t sb = smem_u32(dsm);
    uint32_t sbA = sb, sbB = sb + SM_A_SZ;
    int t = threadIdx.x;
    int lane = t & 31, wid = t >> 5;
    int warp_m = wid >> 2, warp_n = wid & 3;
    int m0 = blockIdx.x * 128;

    // ---- load A tile (128 x 128 halves), one commit group ----
#pragma unroll
    for (int j = 0; j < 8; j++) {
        int lin = t + j * 256;               // 0..2047
        int row = lin >> 4, q = lin & 15;    // 16 x 16B per row
        const __half* gp = A + (size_t)(m0 + row) * DIM + q * 8;
        uint32_t db = sbA + row * A_STR + q * 16;
        asm volatile("cp.async.ca.shared.global [%0], [%1], 16;"
                     :: "r"(db), "l"(gp) : "memory");
    }
    asm volatile("cp.async.commit_group;" ::: "memory");

    // ---- B chunk issue: chunk kcg = nt*2 + kc (16 total), buf = kcg&1 ----
#define ISSUE_B(kcg_)                                                          \
    {                                                                          \
        _Pragma("unroll")                                                      \
        for (int j = 0; j < 4; j++) {                                          \
            int lin = t + j * 256;            /* 0..1023 */                    \
            int row = lin >> 3, q = lin & 7;  /* 8 x 16B per row */            \
            const __half* gp = B + (size_t)(((kcg_) >> 1) * 128 + row) * DIM   \
                                 + ((kcg_) & 1) * 64 + q * 8;                  \
            uint32_t db = sbB + ((kcg_) & 1) * B_TILE + row * B_STR + q * 16;  \
            asm volatile("cp.async.ca.shared.global [%0], [%1], 16;"           \
                         :: "r"(db), "l"(gp) : "memory");                      \
        }                                                                      \
        asm volatile("cp.async.commit_group;" ::: "memory");                   \
    }

    ISSUE_B(0);
    ISSUE_B(1);
    asm volatile("cp.async.wait_group 1;" ::: "memory");   // A + chunk0 ready
    __syncthreads();

    float acc[4][4][4] = {};   // [mt][nsub][4]

#pragma unroll
    for (int kcg = 0; kcg < 16; kcg++) {
        int kc = kcg & 1;
        uint32_t bbase = sbB + kc * B_TILE;
        // ---- compute chunk kcg (BK=64 => 4 k16 steps) ----
#pragma unroll
        for (int ks = 0; ks < 4; ks++) {
            uint32_t bf[2][4];
            int brow = warp_n * 32 + ((lane >> 4) & 1) * 8 + (lane & 7);
            uint32_t bcol = ks * 32 + ((lane >> 3) & 1) * 16;
#pragma unroll
            for (int pr = 0; pr < 2; pr++)
                ldsm_x4(bf[pr], bbase + (brow + pr * 16) * B_STR + bcol);
#pragma unroll
            for (int mt = 0; mt < 4; mt++) {
                uint32_t af[4];
                int arow = warp_m * 64 + mt * 16 + (lane & 15);
                uint32_t aoff = arow * A_STR + kc * 128 + ks * 32 + (lane >> 4) * 16;
                ldsm_x4(af, sbA + aoff);
#pragma unroll
                for (int ns = 0; ns < 4; ns++)
                    mma16816(acc[mt][ns], af, &bf[ns >> 1][(ns & 1) * 2]);
            }
        }
        // ---- epilogue after each nt pair (kc==1) ----
        if (kc == 1) {
            int n0 = (kcg >> 1) * 128;
            int group = lane >> 2, tig = lane & 3;
#pragma unroll
            for (int mt = 0; mt < 4; mt++) {
#pragma unroll
                for (int half = 0; half < 2; half++) {
                    int row = m0 + warp_m * 64 + mt * 16 + group + half * 8;
                    if (row < NN) {
#pragma unroll
                        for (int ns = 0; ns < 4; ns++) {
                            int col = n0 + warp_n * 32 + ns * 8 + 2 * tig;
                            __half2 hv = __floats2half2_rn(acc[mt][ns][half * 2 + 0],
                                                           acc[mt][ns][half * 2 + 1]);
                            *(__half2*)(Y + (size_t)row * NOUT + col) = hv;
                        }
                    }
                }
            }
#pragma unroll
            for (int mt = 0; mt < 4; mt++)
#pragma unroll
                for (int ns = 0; ns < 4; ns++)
#pragma unroll
                    for (int c = 0; c < 4; c++)
                        acc[mt][ns][c] = 0.f;
        }
        __syncthreads();                      // all warps done reading buf kcg&1
        if (kcg + 2 < 16) ISSUE_B(kcg + 2);   // refill the buffer just freed
        if (kcg + 1 < 16) {
            if (kcg + 2 < 16) asm volatile("cp.async.wait_group 1;" ::: "memory");
            else              asm volatile("cp.async.wait_group 0;" ::: "memory");
            __syncthreads();
        }
    }
#undef ISSUE_B
}

// ---------------- CSR scans ----------------
__global__ void scan1() {
    __shared__ int s[256];
    int t = threadIdx.x;
    int v = g_cnt[blockIdx.x * 256 + t];
    s[t] = v; __syncthreads();
#pragma unroll
    for (int o = 1; o < 256; o <<= 1) {
        int x = (t >= o) ? s[t - o] : 0; __syncthreads();
        s[t] += x; __syncthreads();
    }
    if (t == 255) g_bsum[blockIdx.x] = s[255];
}
__global__ void scan2() {
    __shared__ int s[256];
    int t = threadIdx.x;
    int v = (t < NBLK) ? g_bsum[t] : 0;
    s[t] = v; __syncthreads();
#pragma unroll
    for (int o = 1; o < 256; o <<= 1) {
        int x = (t >= o) ? s[t - o] : 0; __syncthreads();
        s[t] += x; __syncthreads();
    }
    if (t < NBLK) g_bpre[t] = s[t] - v;
}
__global__ void scan3() {
    __shared__ int s[256];
    int t = threadIdx.x;
    int i = blockIdx.x * 256 + t;
    int v = g_cnt[i];
    s[t] = v; __syncthreads();
#pragma unroll
    for (int o = 1; o < 256; o <<= 1) {
        int x = (t >= o) ? s[t - o] : 0; __syncthreads();
        s[t] += x; __syncthreads();
    }
    g_off[i] = g_bpre[blockIdx.x] + s[t] - v;
    if (i == NBLK * 256 - 1) g_off[NBLK * 256] = NE;
}
__global__ void permute(const int* __restrict__ src, const int* __restrict__ dst,
                        const int* __restrict__ et, const float* __restrict__ w) {
    int e = blockIdx.x * blockDim.x + threadIdx.x;
    if (e >= NE) return;
    int d = dst[e];
    int p = atomicAdd(&g_pos[d], 1);
    g_psr[p] = (et[e] << 24) | src[e];
    g_pw[p]  = w[e];
}

// ---------------- gather: one warp per node, 4-wide edge unroll ----------------
// TO_A=true:  g_A[n,:] = fp16(relu(bias + sum))   (feeds layer-2 GEMM)
// TO_A=false: out[n,:] = fp32(bias + sum)
template<bool TO_A>
__global__ void __launch_bounds__(256) gather(const __half* __restrict__ Y,
                                              const float* __restrict__ bias,
                                              float* __restrict__ outf,
                                              __half* __restrict__ outh) {
    int wid = threadIdx.x >> 5, lane = threadIdx.x & 31;
    int n = blockIdx.x * 8 + wid;
    if (n >= NN) return;
    int beg = g_off[n], end = g_off[n + 1];
    float4 acc = *(const float4*)(bias + lane * 4);
    int j = beg;
// NOTE: macro parameter named 'wgt' (NOT 'w') to avoid capturing the .w member access.
#define ACCUM(v, wgt)                                                    \
        {                                                                \
            float2 f0 = __half22float2(*(const __half2*)&(v).x);         \
            float2 f1 = __half22float2(*(const __half2*)&(v).y);         \
            acc.x = fmaf((wgt), f0.x, acc.x);                            \
            acc.y = fmaf((wgt), f0.y, acc.y);                            \
            acc.z = fmaf((wgt), f1.x, acc.z);                            \
            acc.w = fmaf((wgt), f1.y, acc.w);                            \
        }
    for (; j + 4 <= end; j += 4) {
        int s0 = g_psr[j],     s1 = g_psr[j + 1];
        int s2 = g_psr[j + 2], s3 = g_psr[j + 3];
        float w0 = g_pw[j],     w1 = g_pw[j + 1];
        float w2 = g_pw[j + 2], w3 = g_pw[j + 3];
        uint2 v0 = *(const uint2*)(Y + (size_t)(s0 & 0xFFFFFF) * NOUT + (s0 >> 24) * DIM + lane * 4);
        uint2 v1 = *(const uint2*)(Y + (size_t)(s1 & 0xFFFFFF) * NOUT + (s1 >> 24) * DIM + lane * 4);
        uint2 v2 = *(const uint2*)(Y + (size_t)(s2 & 0xFFFFFF) * NOUT + (s2 >> 24) * DIM + lane * 4);
        uint2 v3 = *(const uint2*)(Y + (size_t)(s3 & 0xFFFFFF) * NOUT + (s3 >> 24) * DIM + lane * 4);
        ACCUM(v0, w0); ACCUM(v1, w1); ACCUM(v2, w2); ACCUM(v3, w3);
    }
    for (; j < end; j++) {
        int sr = g_psr[j];
        float we = g_pw[j];
        uint2 v = *(const uint2*)(Y + (size_t)(sr & 0xFFFFFF) * NOUT + (sr >> 24) * DIM + lane * 4);
        ACCUM(v, we);
    }
#undef ACCUM
    if (TO_A) {
        __half2 h0 = __floats2half2_rn(fmaxf(acc.x, 0.f), fmaxf(acc.y, 0.f));
        __half2 h1 = __floats2half2_rn(fmaxf(acc.z, 0.f), fmaxf(acc.w, 0.f));
        uint2 o;
        o.x = *(const uint32_t*)&h0;
        o.y = *(const uint32_t*)&h1;
        *(uint2*)(outh + (size_t)n * DIM + lane * 4) = o;
    } else {
        *(float4*)(outf + (size_t)n * DIM + lane * 4) = acc;
    }
}

// ---------------- launch ----------------
extern "C" void kernel_launch(void* const* d_in, const int* in_sizes, int n_in,
                              void* d_out, int out_size) {
    const float* features = (const float*)d_in[0];
    const int*   etypes   = (const int*)d_in[1];
    const float* ew       = (const float*)d_in[2];
    const int*   src      = (const int*)d_in[3];
    const int*   dst      = (const int*)d_in[4];
    const float* comp1    = (const float*)d_in[5];
    const float* V1       = (const float*)d_in[6];
    const float* bias1    = (const float*)d_in[7];
    const float* comp2    = (const float*)d_in[8];
    const float* V2       = (const float*)d_in[9];
    const float* bias2    = (const float*)d_in[10];
    float* out = (float*)d_out;

    __half *Yp, *Ap, *W1p, *W2p;
    int *offp, *posp;
    cudaGetSymbolAddress((void**)&Yp,   g_Y);
    cudaGetSymbolAddress((void**)&Ap,   g_A);
    cudaGetSymbolAddress((void**)&W1p,  g_W1);
    cudaGetSymbolAddress((void**)&W2p,  g_W2);
    cudaGetSymbolAddress((void**)&offp, g_off);
    cudaGetSymbolAddress((void**)&posp, g_pos);

    cudaFuncSetAttribute(gemm_y, cudaFuncAttributeMaxDynamicSharedMemorySize, SM_TOT);

    const int GGRID = (NN + 127) / 128;   // 391
    const int GB = (NN + 7) / 8;          // 6250
    const int CB = NN * 32 / 256;         // 6250

    // Harness issues 2 internal launches first; our #4 = global #6 (ncu -s 5 -c 1).
    compute_Wt<<<512, 256>>>(comp1, V1, W1p);                      // 1
    conv_A<<<CB, 256>>>((const float4*)features, (uint2*)Ap);      // 2
    compute_Wt<<<512, 256>>>(comp2, V2, W2p);                      // 3
    gemm_y<<<GGRID, 256, SM_TOT>>>(Ap, W1p, Yp);                   // 4  <- profiled
    zero_cnt<<<NBLK, 256>>>();                                     // 5
    hist<<<(NE + 255) / 256, 256>>>(dst);                          // 6
    scan1<<<NBLK, 256>>>();                                        // 7
    scan2<<<1, 256>>>();                                           // 8
    scan3<<<NBLK, 256>>>();                                        // 9
    cudaMemcpyAsync(posp, offp, NBLK * 256 * sizeof(int), cudaMemcpyDeviceToDevice);
    permute<<<(NE + 255) / 256, 256>>>(src, dst, etypes, ew);      // 10
    gather<true><<<GB, 256>>>(Yp, bias1, nullptr, Ap);             // 11 -> A (relu, fp16)
    gemm_y<<<GGRID, 256, SM_TOT>>>(Ap, W2p, Yp);                   // 12
    gather<false><<<GB, 256>>>(Yp, bias2, out, nullptr);           // 13
}